// round 17
// baseline (speedup 1.0000x reference)
#include <cuda_runtime.h>

#define S 2048
#define DM 512
#define NI 13
#define NC 117

typedef unsigned long long ull;

// ---------------- scratch ----------------
__device__ float  g_Wp[DM * 128];            // padded W, [k][128]
__device__ float4 g_plin[NI * S];            // {x0, y0, cw, sw} lin channel, [i][a]
__device__ float4 g_pang[NI * S];            // ang channel
__device__ float  g_base[NI * S];            // min + noise_bias, [i][b]
__device__ float  g_partial[16 * NI * S];    // [ca][i][b]
__device__ int    g_cnt[NI * 16];            // per-(i,cb) counters (self-resetting)

// ---------------- packed f32x2 helpers (GEMM only) ----------------
#define FMA2_ACC(d, a, b) asm("fma.rn.f32x2 %0, %1, %2, %0;" : "+l"(d) : "l"(a), "l"(b))

__device__ __forceinline__ ull pk2(float lo, float hi) {
    ull r; asm("mov.b64 %0, {%1,%2};" : "=l"(r) : "f"(lo), "f"(hi)); return r;
}
__device__ __forceinline__ void upk2(ull v, float& lo, float& hi) {
    asm("mov.b64 {%0,%1}, %2;" : "=f"(lo), "=f"(hi) : "l"(v));
}

__device__ __forceinline__ float softplus_f(float x) {
    return fmaxf(x, 0.0f) + log1pf(expf(-fabsf(x)));
}

// ---------------- 0) pad W (float4 stores) + zero counters ----------------
__global__ void wprep_kernel(const float* __restrict__ W) {
    int idx4 = blockIdx.x * 256 + threadIdx.x;   // DM*128/4 = 16384
    int k  = idx4 >> 5;
    int c0 = (idx4 & 31) * 4;
    const float* Wr = W + k * NC;
    float4 v;
    v.x = (c0 + 0 < NC) ? Wr[c0 + 0] : 0.0f;
    v.y = (c0 + 1 < NC) ? Wr[c0 + 1] : 0.0f;
    v.z = (c0 + 2 < NC) ? Wr[c0 + 2] : 0.0f;
    v.w = (c0 + 3 < NC) ? Wr[c0 + 3] : 0.0f;
    ((float4*)g_Wp)[idx4] = v;
    if (idx4 < NI * 16) g_cnt[idx4] = 0;
}

// ---------------- 1) fused LN + GEMM(split-K x8) + param transform ------------
// 128 blocks x 512 threads. Block = 16 tokens. Warp w (0..15):
//   tokg = (w&1)*8 tokens, kq = w>>1 -> K-eighth of 64 k.   (R16, measured win)
#define XROW 18
__global__ __launch_bounds__(512) void gemm_fused(
    const float* __restrict__ h, const float* __restrict__ mn,
    const float* __restrict__ lw, const float* __restrict__ lb,
    const float* __restrict__ bias)
{
    __shared__ __align__(16) float xsT[DM * XROW];   // 36.9 KB; reused as ps4 later

    int t  = threadIdx.x;
    int s0 = blockIdx.x * 16;

    // ---- LayerNorm: one warp per row, 16 rows; store TRANSPOSED ----
    {
        int r = t >> 5, sub = t & 31;
        const float4* h4 = (const float4*)h;
        float4 v[4];
        float sum = 0.f, sq = 0.f;
        #pragma unroll
        for (int q = 0; q < 4; q++) {
            v[q] = h4[(s0 + r) * (DM / 4) + sub + q * 32];
            sum += v[q].x + v[q].y + v[q].z + v[q].w;
            sq  += v[q].x * v[q].x + v[q].y * v[q].y + v[q].z * v[q].z + v[q].w * v[q].w;
        }
        #pragma unroll
        for (int o = 16; o; o >>= 1) {
            sum += __shfl_xor_sync(0xffffffffu, sum, o);
            sq  += __shfl_xor_sync(0xffffffffu, sq,  o);
        }
        float mu   = sum * (1.0f / DM);
        float var  = sq * (1.0f / DM) - mu * mu;
        float rstd = rsqrtf(var + 1e-5f);
        const float4* lw4 = (const float4*)lw;
        const float4* lb4 = (const float4*)lb;
        #pragma unroll
        for (int q = 0; q < 4; q++) {
            float4 wv = lw4[sub + q * 32], bv = lb4[sub + q * 32];
            int k0 = (sub + q * 32) * 4;
            xsT[(k0 + 0) * XROW + r] = (v[q].x - mu) * rstd * wv.x + bv.x;
            xsT[(k0 + 1) * XROW + r] = (v[q].y - mu) * rstd * wv.y + bv.y;
            xsT[(k0 + 2) * XROW + r] = (v[q].z - mu) * rstd * wv.z + bv.z;
            xsT[(k0 + 3) * XROW + r] = (v[q].w - mu) * rstd * wv.w + bv.w;
        }
    }
    __syncthreads();

    // ---- GEMM: warp = 8 tokens (4 pairs) x 128 cols, over its K-eighth ----
    int lane = t & 31, w = t >> 5;
    int tokg = (w & 1) * 8, kq = w >> 1;   // kq 0..7
    ull A[4][4];
    #pragma unroll
    for (int p = 0; p < 4; p++)
        #pragma unroll
        for (int q = 0; q < 4; q++) A[p][q] = 0ULL;

    const float4* Wp4 = (const float4*)g_Wp;
    int kbeg = kq * 64, kend = kbeg + 64;
    #pragma unroll 8
    for (int k = kbeg; k < kend; k++) {
        ull x01 = *(const ull*)&xsT[k * XROW + tokg + 0];
        ull x23 = *(const ull*)&xsT[k * XROW + tokg + 2];
        ull x45 = *(const ull*)&xsT[k * XROW + tokg + 4];
        ull x67 = *(const ull*)&xsT[k * XROW + tokg + 6];
        float4 wv = Wp4[k * 32 + lane];
        ull wd0 = pk2(wv.x, wv.x), wd1 = pk2(wv.y, wv.y);
        ull wd2 = pk2(wv.z, wv.z), wd3 = pk2(wv.w, wv.w);
        FMA2_ACC(A[0][0], x01, wd0); FMA2_ACC(A[0][1], x01, wd1);
        FMA2_ACC(A[0][2], x01, wd2); FMA2_ACC(A[0][3], x01, wd3);
        FMA2_ACC(A[1][0], x23, wd0); FMA2_ACC(A[1][1], x23, wd1);
        FMA2_ACC(A[1][2], x23, wd2); FMA2_ACC(A[1][3], x23, wd3);
        FMA2_ACC(A[2][0], x45, wd0); FMA2_ACC(A[2][1], x45, wd1);
        FMA2_ACC(A[2][2], x45, wd2); FMA2_ACC(A[2][3], x45, wd3);
        FMA2_ACC(A[3][0], x67, wd0); FMA2_ACC(A[3][1], x67, wd1);
        FMA2_ACC(A[3][2], x67, wd2); FMA2_ACC(A[3][3], x67, wd3);
    }
    __syncthreads();   // x no longer needed; reuse xsT as ps4[4][16][128]

    // ---- combine round 1: kq 0..3 store per-quarter partials ----
    float* ps4 = xsT;
    if (kq < 4) {
        #pragma unroll
        for (int p = 0; p < 4; p++) {
            #pragma unroll
            for (int q = 0; q < 4; q++) {
                float e0, e1; upk2(A[p][q], e0, e1);
                int c = 4 * lane + q;
                int tok0 = tokg + 2 * p;
                ps4[(kq * 16 + tok0) * 128 + c]     = e0;
                ps4[(kq * 16 + tok0 + 1) * 128 + c] = e1;
            }
        }
    }
    __syncthreads();
    // ---- combine round 2: kq 4..7 add into slots 0..3 ----
    if (kq >= 4) {
        int slot = kq - 4;
        #pragma unroll
        for (int p = 0; p < 4; p++) {
            #pragma unroll
            for (int q = 0; q < 4; q++) {
                float e0, e1; upk2(A[p][q], e0, e1);
                int c = 4 * lane + q;
                int tok0 = tokg + 2 * p;
                ps4[(slot * 16 + tok0) * 128 + c]     += e0;
                ps4[(slot * 16 + tok0 + 1) * 128 + c] += e1;
            }
        }
    }
    __syncthreads();

    // ---- sum 4 slots into slot 0 (ps[tok][c]); 2048 float4 over 512 thr ----
    {
        float4* q0 = (float4*)ps4;
        float4 a = q0[t];
        float4 b = q0[512 + t];
        float4 c = q0[1024 + t];
        float4 d = q0[1536 + t];
        a.x += b.x + c.x + d.x;
        a.y += b.y + c.y + d.y;
        a.z += b.z + c.z + d.z;
        a.w += b.w + c.w + d.w;
        q0[t] = a;
    }
    __syncthreads();

    // ---- param transform: 16 tokens x 13 imus x 2 channels = 416 units ----
    float* ps = ps4;
    if (t < 16 * NI * 2) {
        int u = t;
        int r   = u / (2 * NI);
        int rem = u - r * 2 * NI;
        int i = rem >> 1, ch = rem & 1;
        int s = s0 + r;
        const float* P = ps + r * 128;
        int ck  = (ch ? 2 : 0) * NI + i;
        int cd  = (ch ? 3 : 1) * NI + i;
        int cc  = (ch ? 5 : 4) * NI + i;
        int cph = (ch ? 7 : 6) * NI + i;
        float pk  = P[ck]  + bias[ck];
        float pd  = P[cd]  + bias[cd];
        float pc  = P[cc]  + bias[cc];
        float pph = P[cph] + bias[cph];

        float d  = sqrtf(pd * pd + 1e-5f);
        float sp = softplus_f(pk);
        float kk = d * d * 0.25f + sp;
        float om = 0.5f * sqrtf(fmaxf(4.0f * kk - d * d, 0.0f));
        float dec = expf(-0.5f * d);
        float so, co; sincosf(om, &so, &co);
        float sph, cph_; sincosf(pph, &sph, &cph_);
        float4 v = make_float4(pc * cph_, pc * sph, dec * co, dec * so);
        if (ch) g_pang[i * S + s] = v;
        else {
            g_plin[i * S + s] = v;
            int c8 = 8 * NI + i;
            g_base[i * S + s] = mn[0] + P[c8] + bias[c8];
        }
    }
}

// ---------------- 2) triangular sweep: SCALAR float hot path ----------------
// smem: float buffer 32 b-slots x stride 33 = 4224 B.
// Store: sbuf[bb*33 + lane] bank (bb+lane)&31, conflict-free.
// Fold:  lane reads row lane: sbuf[lane*33 + c], bank (lane+c)&31, conflict-free.

__device__ __forceinline__ void fold32(const float* sbuf, float* pout, int lane) {
    const float* row = sbuf + lane * 33;
    float a0 = 0.f, a1 = 0.f, a2 = 0.f, a3 = 0.f;
    #pragma unroll
    for (int c = 0; c < 32; c += 4) {
        a0 += row[c + 0];
        a1 += row[c + 1];
        a2 += row[c + 2];
        a3 += row[c + 3];
    }
    pout[lane] = (a0 + a1) + (a2 + a3);
}

// steady tile: 8 scalar states/lane, double-step (emit b, b+1; rotate by w^2)
__device__ __forceinline__ void run_full(int a0, int b0, int i, float* pout,
                                         int lane, float* sbuf) {
    float x[8], y[8], cw[8], sw[8], cw2[8], sw2[8];
    #pragma unroll
    for (int j = 0; j < 4; j++) {
        int a = a0 + j * 32 + lane;
        float4 pl = g_plin[i * S + a];
        float4 pa = g_pang[i * S + a];
        cw[2*j]   = pl.z; sw[2*j]   = pl.w;
        cw[2*j+1] = pa.z; sw[2*j+1] = pa.w;
        unsigned e0 = (unsigned)(b0 - a);
        #pragma unroll
        for (int c = 0; c < 2; c++) {
            int s = 2 * j + c;
            float x0 = c ? pa.x : pl.x;
            float y0 = c ? pa.y : pl.y;
            // scalar branchless binexp: (rx,ry) = (cw,sw)^e0
            float rx = 1.f, ry = 0.f, bx = cw[s], by = sw[s];
            unsigned e = e0;
            #pragma unroll
            for (int it = 0; it < 11; it++) {
                float tx = rx * bx - ry * by;
                float ty = rx * by + ry * bx;
                bool m = (e & 1u) != 0u;
                rx = m ? tx : rx;
                ry = m ? ty : ry;
                e >>= 1;
                float tb = bx * by;
                bx = bx * bx - by * by;
                by = tb + tb;
            }
            x[s] = x0 * rx - y0 * ry;
            y[s] = x0 * ry + y0 * rx;
            cw2[s] = cw[s] * cw[s] - sw[s] * sw[s];
            sw2[s] = 2.0f * cw[s] * sw[s];
        }
    }
    #pragma unroll 1
    for (int chunk = 0; chunk < 4; chunk++) {
        #pragma unroll
        for (int it = 0; it < 16; it++) {
            int bb0 = it * 2;
            float sA = ((y[0] + y[1]) + (y[2] + y[3])) + ((y[4] + y[5]) + (y[6] + y[7]));
            sbuf[bb0 * 33 + lane] = sA;
            float b0s = x[0] * sw[0] + y[0] * cw[0];
            float b1s = x[1] * sw[1] + y[1] * cw[1];
            float b2s = x[2] * sw[2] + y[2] * cw[2];
            float b3s = x[3] * sw[3] + y[3] * cw[3];
            float b4s = x[4] * sw[4] + y[4] * cw[4];
            float b5s = x[5] * sw[5] + y[5] * cw[5];
            float b6s = x[6] * sw[6] + y[6] * cw[6];
            float b7s = x[7] * sw[7] + y[7] * cw[7];
            float sB = ((b0s + b1s) + (b2s + b3s)) + ((b4s + b5s) + (b6s + b7s));
            sbuf[(bb0 + 1) * 33 + lane] = sB;
            #pragma unroll
            for (int s = 0; s < 8; s++) {
                float nx = x[s] * cw2[s] - y[s] * sw2[s];
                float ny = x[s] * sw2[s] + y[s] * cw2[s];
                x[s] = nx; y[s] = ny;
            }
        }
        __syncwarp();
        fold32(sbuf, pout + chunk * 32, lane);
        __syncwarp();
    }
}

// diagonal tile: 8 scalar states/lane, 128 single steps with birth predicate
__device__ __forceinline__ void run_diag(int b0, int i, float* pout,
                                         int lane, float* sbuf) {
    float x[8], y[8], x0v[8], y0v[8], cw[8], sw[8];
    int aj[4];
    #pragma unroll
    for (int j = 0; j < 4; j++) {
        int a = b0 + j * 32 + lane;
        aj[j] = a;
        float4 pl = g_plin[i * S + a];
        float4 pa = g_pang[i * S + a];
        cw[2*j]   = pl.z; sw[2*j]   = pl.w;
        cw[2*j+1] = pa.z; sw[2*j+1] = pa.w;
        x0v[2*j]   = pl.x; y0v[2*j]   = pl.y;
        x0v[2*j+1] = pa.x; y0v[2*j+1] = pa.y;
        x[2*j] = 0.f; y[2*j] = 0.f; x[2*j+1] = 0.f; y[2*j+1] = 0.f;
    }
    #pragma unroll 1
    for (int chunk = 0; chunk < 4; chunk++) {
        #pragma unroll
        for (int bb = 0; bb < 32; bb++) {
            int b = b0 + chunk * 32 + bb;
            #pragma unroll
            for (int s = 0; s < 8; s++) {
                bool hit = (b == aj[s >> 1]);
                x[s] = hit ? x0v[s] : x[s];
                y[s] = hit ? y0v[s] : y[s];
            }
            float sA = ((y[0] + y[1]) + (y[2] + y[3])) + ((y[4] + y[5]) + (y[6] + y[7]));
            sbuf[bb * 33 + lane] = sA;
            #pragma unroll
            for (int s = 0; s < 8; s++) {
                float nx = x[s] * cw[s] - y[s] * sw[s];
                float ny = x[s] * sw[s] + y[s] * cw[s];
                x[s] = nx; y[s] = ny;
            }
        }
        __syncwarp();
        fold32(sbuf, pout + chunk * 32, lane);
        __syncwarp();
    }
}

// grid (136, 13): slot -> (ca, cb) triangular, ca <= cb. Last tile of a
// (i, cb) column (cb+1 tiles) folds base + partials -> out, resets counter.
__global__ __launch_bounds__(32) void sweep_kernel(float* __restrict__ out) {
    __shared__ float sbuf[32 * 33];   // 4224 B
    int slot = blockIdx.x, i = blockIdx.y;
    int lane = threadIdx.x;
    int s = slot, cb = 0;
    while (s > cb) { s -= (cb + 1); cb++; }
    int ca = s;
    float* pout = g_partial + (ca * NI + i) * S + cb * 128;
    if (ca == cb) run_diag(cb * 128, i, pout, lane, sbuf);
    else          run_full(ca * 128, cb * 128, i, pout, lane, sbuf);

    // fused fold: last tile of (i, cb) column writes the output
    __threadfence();
    int last = 0;
    if (lane == 0)
        last = (atomicAdd(&g_cnt[i * 16 + cb], 1) == cb);
    last = __shfl_sync(0xffffffffu, last, 0);
    if (last) {
        __threadfence();
        #pragma unroll
        for (int g = 0; g < 4; g++) {
            int b = cb * 128 + g * 32 + lane;
            float acc = g_base[i * S + b];
            #pragma unroll
            for (int c2 = 0; c2 < 16; c2++)
                if (c2 <= cb) acc += g_partial[(c2 * NI + i) * S + b];
            out[i * S + b] = acc;
        }
        if (lane == 0) g_cnt[i * 16 + cb] = 0;   // self-reset for next replay
    }
}

// ---------------- launch ----------------
extern "C" void kernel_launch(void* const* d_in, const int* in_sizes, int n_in,
                              void* d_out, int out_size) {
    const float* h    = (const float*)d_in[0];
    const float* mn   = (const float*)d_in[1];
    const float* lw   = (const float*)d_in[2];
    const float* lb   = (const float*)d_in[3];
    const float* W    = (const float*)d_in[4];
    const float* bias = (const float*)d_in[5];
    float* out = (float*)d_out;

    wprep_kernel<<<64, 256>>>(W);
    gemm_fused<<<S / 16, 512>>>(h, mn, lw, lb, bias);
    dim3 g(136, NI);
    sweep_kernel<<<g, 32>>>(out);
}